// round 5
// baseline (speedup 1.0000x reference)
#include <cuda_runtime.h>

#define NTRAJ 2048
#define TSTEPS 512
#define KDIM   (TSTEPS * 3)   // 1536 floats per trajectory
#define PF 8                  // prefetch depth per chain

// Transposed measurements: [t*3+k][traj] for coalesced mainloop loads. 12 MB.
__device__ float g_zt[KDIM * NTRAJ];

// Tiled transpose: meas[traj][rem] -> g_zt[rem][traj], both sides coalesced.
__global__ void transpose_k(const float* __restrict__ meas) {
    __shared__ float tile[32][33];
    int rem0  = blockIdx.x * 32;
    int traj0 = blockIdx.y * 32;
    int r  = rem0 + threadIdx.x;
    int tj = traj0 + threadIdx.y;
    tile[threadIdx.y][threadIdx.x] = meas[tj * KDIM + r];
    __syncthreads();
    r  = rem0 + threadIdx.y;
    tj = traj0 + threadIdx.x;
    g_zt[r * NTRAJ + tj] = tile[threadIdx.x][threadIdx.y];
}

__device__ __forceinline__ float htanh(float x) {
    float y;
    asm("tanh.approx.f32 %0, %1;" : "=f"(y) : "f"(x));
    return y;
}
__device__ __forceinline__ float frcp(float x) {
    float y;
    asm("rcp.approx.f32 %0, %1;" : "=f"(y) : "f"(x));
    return y;
}

// One 2x2 Kalman block step for one chain; returns combined loss (valid on c=0 lanes).
__device__ __forceinline__ float kstep(
    float& s0, float& s1, float& p00, float& p01, float& p11,
    float z, float dt, float c1, float c2, float c3, float c4,
    float q0, float q1, float r)
{
    float sp = fmaf(dt, s1, s0);
    float tv = htanh(100.0f * s1);
    float vp = fmaf(-c2, tv, c1 * s1);
    float a  = fmaf(c3, tv * tv, c4);

    float u   = fmaf(dt, p11, p01);
    float n00 = fmaf(dt, u, fmaf(dt, p01, p00)) + q0;
    float n01 = a * u;
    float n11 = fmaf(a * a, p11, q1);

    float S  = n00 + r;
    float is = frcp(S);
    float yv = z - sp;
    float K0 = n00 * is;
    float K1 = n01 * is;
    s0 = fmaf(K0, yv, sp);
    s1 = fmaf(K1, yv, vp);
    float om = 1.0f - K0;
    p00 = om * n00;
    p01 = om * n01;
    p11 = fmaf(-K1, n01, n11);

    float mah = yv * (is * yv);
    float S8  = __shfl_down_sync(0xFFFFFFFFu, S, 8);
    float S16 = __shfl_down_sync(0xFFFFFFFFu, S, 16);
    float m8  = __shfl_down_sync(0xFFFFFFFFu, mah, 8);
    float m16 = __shfl_down_sync(0xFFFFFFFFu, mah, 16);
    return fmaf(S * S8, S16, (mah + m8) + m16);
}

// One warp handles 16 trajectories: lanes (c = lane>>3, j = lane&7) each run
// TWO independent 2x2 Kalman chains (traj j and traj j+8 of the block's 16),
// interleaved so one chain's stalls are filled by the other's instructions.
__global__ void __launch_bounds__(32) ekf_k(
    const float* __restrict__ init_state,
    const float* __restrict__ dyna,
    const float* __restrict__ Q,
    const float* __restrict__ R,
    const float* __restrict__ P0,
    float* __restrict__ out)
{
    const int lane = threadIdx.x & 31;
    int c = lane >> 3; if (c > 2) c = 2;
    const int j     = lane & 7;
    const int trajA = blockIdx.x * 16 + j;
    const int trajB = trajA + 8;

    const float dt = 1.0f / 120.0f;

    const bool lin = (c == 2);
    const float fric = lin ? 0.0f : __ldg(dyna + 0);
    const float damp = lin ? 0.0f : __ldg(dyna + 1);

    const float c1 = 1.0f - dt * damp;
    const float c2 = dt * fric;
    const float c3 = 100.0f * c2;
    const float c4 = c1 - c3;

    const int pc = lin ? 4 : c;
    const int vc = lin ? 5 : c + 2;

    const float q0 = __ldg(Q + pc * 7);
    const float q1 = __ldg(Q + vc * 7);
    const float r  = __ldg(R + c * 4);

    float s0A = init_state[trajA * 6 + pc], s1A = init_state[trajA * 6 + vc];
    float s0B = init_state[trajB * 6 + pc], s1B = init_state[trajB * 6 + vc];

    const float P0a = __ldg(P0 + pc * 7);
    const float P0b = __ldg(P0 + pc * 6 + vc);
    const float P0c = __ldg(P0 + vc * 7);
    float p00A = P0a, p01A = P0b, p11A = P0c;
    float p00B = P0a, p01B = P0b, p11B = P0c;

    const float* zbA = g_zt + c * NTRAJ + trajA;
    const float* zbB = g_zt + c * NTRAJ + trajB;
    float* oA = out + trajA * TSTEPS;
    float* oB = out + trajB * TSTEPS;

    float zrA[PF], zrB[PF];
    #pragma unroll
    for (int i = 0; i < PF; ++i) {
        zrA[i] = zbA[3 * i * NTRAJ];
        zrB[i] = zbB[3 * i * NTRAJ];
    }

    float lA0, lA1, lA2, lB0, lB1, lB2;

    #pragma unroll 1
    for (int t = 0; t < TSTEPS; t += PF) {
        #pragma unroll
        for (int u8 = 0; u8 < PF; ++u8) {
            const int t_ = t + u8;
            float zA = zrA[u8];
            float zB = zrB[u8];

            // prefetch PF ahead; clamp address at the tail (values unused)
            int tn = t_ + PF; if (tn > TSTEPS - 1) tn = TSTEPS - 1;
            zrA[u8] = zbA[3 * tn * NTRAJ];
            zrB[u8] = zbB[3 * tn * NTRAJ];

            float lossA = kstep(s0A, s1A, p00A, p01A, p11A, zA,
                                dt, c1, c2, c3, c4, q0, q1, r);
            float lossB = kstep(s0B, s1B, p00B, p01B, p11B, zB,
                                dt, c1, c2, c3, c4, q0, q1, r);

            const int ph = u8 & 3;
            if (ph == 0)      { lA0 = lossA; lB0 = lossB; }
            else if (ph == 1) { lA1 = lossA; lB1 = lossB; }
            else if (ph == 2) { lA2 = lossA; lB2 = lossB; }
            else if (lane < 8) {
                *reinterpret_cast<float4*>(oA + (t_ - 3)) =
                    make_float4(lA0, lA1, lA2, lossA);
                *reinterpret_cast<float4*>(oB + (t_ - 3)) =
                    make_float4(lB0, lB1, lB2, lossB);
            }
        }
    }
}

extern "C" void kernel_launch(void* const* d_in, const int* in_sizes, int n_in,
                              void* d_out, int out_size) {
    const float* meas = (const float*)d_in[0];
    const float* init = (const float*)d_in[1];
    const float* dyna = (const float*)d_in[2];
    const float* Q    = (const float*)d_in[3];
    const float* R    = (const float*)d_in[4];
    const float* P0   = (const float*)d_in[5];
    float* out = (float*)d_out;

    dim3 tgrid(KDIM / 32, NTRAJ / 32);
    dim3 tblk(32, 32);
    transpose_k<<<tgrid, tblk>>>(meas);
    ekf_k<<<NTRAJ / 16, 32>>>(init, dyna, Q, R, P0, out);
}

// round 6
// speedup vs baseline: 1.8180x; 1.8180x over previous
#include <cuda_runtime.h>

#define NTRAJ 2048
#define TSTEPS 512
#define KDIM   (TSTEPS * 3)
#define PF 8

// Transposed measurements: [t*3+k][traj]. 12 MB.
__device__ float g_zt[KDIM * NTRAJ];
// Dump target for non-writer lanes (branch-free store). Never read.
__device__ float4 g_dump[256 * 32];

__global__ void transpose_k(const float* __restrict__ meas) {
    __shared__ float tile[32][33];
    int rem0  = blockIdx.x * 32;
    int traj0 = blockIdx.y * 32;
    tile[threadIdx.y][threadIdx.x] = meas[(traj0 + threadIdx.y) * KDIM + rem0 + threadIdx.x];
    __syncthreads();
    g_zt[(rem0 + threadIdx.y) * NTRAJ + traj0 + threadIdx.x] = tile[threadIdx.x][threadIdx.y];
}

__device__ __forceinline__ float htanh(float x) {
    float y;
    asm("tanh.approx.f32 %0, %1;" : "=f"(y) : "f"(x));
    return y;
}
// rcp.approx + 1 Newton step: matches IEEE 1/x to <=1 ulp, shorter than __frcp_rn.
__device__ __forceinline__ float frcp_nr(float x) {
    float y;
    asm("rcp.approx.f32 %0, %1;" : "=f"(y) : "f"(x));
    float e = fmaf(-x, y, 1.0f);
    return fmaf(e, y, y);
}

// One warp = 8 trajectories; lanes (c = lane>>3, j = lane&7) run the c-th
// independent 2x2 Kalman block. Branch-free mainloop: clamped prefetch,
// deferred 4-step shuffle combine, select-address stores.
__global__ void __launch_bounds__(32) ekf_k(
    const float* __restrict__ init_state,
    const float* __restrict__ dyna,
    const float* __restrict__ Q,
    const float* __restrict__ R,
    const float* __restrict__ P0,
    float* __restrict__ out)
{
    const int lane = threadIdx.x & 31;
    int c = lane >> 3; if (c > 2) c = 2;
    const int j    = lane & 7;
    const int traj = blockIdx.x * 8 + j;

    const float dt = 1.0f / 120.0f;

    const bool lin = (c == 2);
    const float fric = lin ? 0.0f : __ldg(dyna + 0);
    const float damp = lin ? 0.0f : __ldg(dyna + 1);

    const float c1 = 1.0f - dt * damp;
    const float c2 = dt * fric;
    const float c3 = 100.0f * c2;
    const float c4 = c1 - c3;

    const int pc = lin ? 4 : c;
    const int vc = lin ? 5 : c + 2;

    const float q0 = __ldg(Q + pc * 7);
    const float q1 = __ldg(Q + vc * 7);
    const float r  = __ldg(R + c * 4);

    float s0 = init_state[traj * 6 + pc];
    float s1 = init_state[traj * 6 + vc];

    float p00 = __ldg(P0 + pc * 7);
    float p01 = __ldg(P0 + pc * 6 + vc);
    float p11 = __ldg(P0 + vc * 7);

    const float* zb = g_zt + c * NTRAJ + traj;
    float* o = out + traj * TSTEPS;

    // Branch-free store target: lanes 0-7 write real output, others dump.
    float4* dump = g_dump + (blockIdx.x * 32 + lane);

    float zr[PF];
    #pragma unroll
    for (int i = 0; i < PF; ++i) zr[i] = zb[3 * i * NTRAJ];

    float Sb[4], Mb[4];

    #pragma unroll 1
    for (int t = 0; t < TSTEPS; t += PF) {
        #pragma unroll
        for (int u8 = 0; u8 < PF; ++u8) {
            const int t_ = t + u8;
            float z = zr[u8];

            // unconditional prefetch, clamped address (tail loads unused)
            int tn = t_ + PF; tn = (tn > TSTEPS - 1) ? (TSTEPS - 1) : tn;
            zr[u8] = zb[3 * tn * NTRAJ];

            // ---- predict ----
            float sp = fmaf(dt, s1, s0);
            float tv = htanh(100.0f * s1);
            float vp = fmaf(-c2, tv, c1 * s1);
            float a  = fmaf(c3, tv * tv, c4);

            float u   = fmaf(dt, p11, p01);
            float n00 = fmaf(dt, u, fmaf(dt, p01, p00)) + q0;
            float n01 = a * u;
            float n11 = fmaf(a * a, p11, q1);

            // ---- update ----
            float S  = n00 + r;
            float is = frcp_nr(S);
            float yv = z - sp;
            float K0 = __fmul_rn(n00, is);
            float K1 = __fmul_rn(n01, is);
            s0 = fmaf(K0, yv, sp);
            s1 = fmaf(K1, yv, vp);
            float om = 1.0f - K0;
            p00 = om * n00;
            p01 = om * n01;
            p11 = fmaf(-K1, n01, n11);

            const int ph = u8 & 3;           // compile-time under unroll
            Sb[ph] = S;
            Mb[ph] = yv * (is * yv);

            if (ph == 3) {
                // deferred combine: operands ready -> shuffle latency hidden
                float l0, l1, l2, l3;
                {
                    float S8  = __shfl_down_sync(0xFFFFFFFFu, Sb[0], 8);
                    float S16 = __shfl_down_sync(0xFFFFFFFFu, Sb[0], 16);
                    float m8  = __shfl_down_sync(0xFFFFFFFFu, Mb[0], 8);
                    float m16 = __shfl_down_sync(0xFFFFFFFFu, Mb[0], 16);
                    l0 = fmaf(Sb[0] * S8, S16, (Mb[0] + m8) + m16);
                }
                {
                    float S8  = __shfl_down_sync(0xFFFFFFFFu, Sb[1], 8);
                    float S16 = __shfl_down_sync(0xFFFFFFFFu, Sb[1], 16);
                    float m8  = __shfl_down_sync(0xFFFFFFFFu, Mb[1], 8);
                    float m16 = __shfl_down_sync(0xFFFFFFFFu, Mb[1], 16);
                    l1 = fmaf(Sb[1] * S8, S16, (Mb[1] + m8) + m16);
                }
                {
                    float S8  = __shfl_down_sync(0xFFFFFFFFu, Sb[2], 8);
                    float S16 = __shfl_down_sync(0xFFFFFFFFu, Sb[2], 16);
                    float m8  = __shfl_down_sync(0xFFFFFFFFu, Mb[2], 8);
                    float m16 = __shfl_down_sync(0xFFFFFFFFu, Mb[2], 16);
                    l2 = fmaf(Sb[2] * S8, S16, (Mb[2] + m8) + m16);
                }
                {
                    float S8  = __shfl_down_sync(0xFFFFFFFFu, Sb[3], 8);
                    float S16 = __shfl_down_sync(0xFFFFFFFFu, Sb[3], 16);
                    float m8  = __shfl_down_sync(0xFFFFFFFFu, Mb[3], 8);
                    float m16 = __shfl_down_sync(0xFFFFFFFFu, Mb[3], 16);
                    l3 = fmaf(Sb[3] * S8, S16, (Mb[3] + m8) + m16);
                }
                // branch-free store: select address, unconditional STG.128
                float4* dst = (lane < 8)
                            ? reinterpret_cast<float4*>(o + (t_ - 3))
                            : dump;
                *dst = make_float4(l0, l1, l2, l3);
            }
        }
    }
}

extern "C" void kernel_launch(void* const* d_in, const int* in_sizes, int n_in,
                              void* d_out, int out_size) {
    const float* meas = (const float*)d_in[0];
    const float* init = (const float*)d_in[1];
    const float* dyna = (const float*)d_in[2];
    const float* Q    = (const float*)d_in[3];
    const float* R    = (const float*)d_in[4];
    const float* P0   = (const float*)d_in[5];
    float* out = (float*)d_out;

    dim3 tgrid(KDIM / 32, NTRAJ / 32);
    dim3 tblk(32, 32);
    transpose_k<<<tgrid, tblk>>>(meas);
    ekf_k<<<NTRAJ / 8, 32>>>(init, dyna, Q, R, P0, out);
}